// round 2
// baseline (speedup 1.0000x reference)
#include <cuda_runtime.h>
#include <math.h>

// Problem constants
#define BB 4
#define NN 32768
#define KK 16
#define IN_DIM 32
#define HID 64
#define OUT_DIM 32
#define KIN 36
#define KH 64

// Scratch for pointwise-MLP output x: (B, N, 32) floats = 16 MB
__device__ float g_x[BB * NN * OUT_DIM];

// ---------------------------------------------------------------------------
// Constant-bank weights: warp-uniform reads go through the const port (LDC),
// freeing the smem crossbar (which was the R1 bottleneck at 4 cyc / LDS.128
// broadcast). Total ~43 KB < 64 KB constant limit.
// ---------------------------------------------------------------------------
__constant__ float4 cWk1[KIN * KH / 4];       //  9216 B
__constant__ float4 cWk2[KH * KH / 4];        // 16384 B
__constant__ float  cbk1[KH];
__constant__ float  cbk2[KH];
__constant__ float  cbk3[OUT_DIM];
__constant__ float  cG[OUT_DIM];
__constant__ float  cBt[OUT_DIM];
__constant__ float4 cWp1[IN_DIM * HID / 4];   //  8192 B
__constant__ float4 cWp2[HID * OUT_DIM / 4];  //  8192 B
__constant__ float  cbp1[HID];
__constant__ float  cbp2[OUT_DIM];

__device__ __forceinline__ float gelu_exact(float v) {
    return 0.5f * v * (1.0f + erff(v * 0.7071067811865476f));
}

// ---------------------------------------------------------------------------
// Kernel 1: pointwise MLP  x = gelu(inp@Wp1+bp1)@Wp2+bp2  (one thread per (b,n))
// Weights from constant bank.
// ---------------------------------------------------------------------------
__global__ __launch_bounds__(256) void pointwise_kernel(
    const float* __restrict__ inp)
{
    int t = blockIdx.x * 256 + threadIdx.x;   // 0 .. B*N-1
    const float4* ir = (const float4*)(inp + t * IN_DIM);

    float in[IN_DIM];
#pragma unroll
    for (int i = 0; i < IN_DIM / 4; ++i) {
        float4 v = ir[i];
        in[4*i+0] = v.x; in[4*i+1] = v.y; in[4*i+2] = v.z; in[4*i+3] = v.w;
    }

    float h[HID];
#pragma unroll
    for (int o4 = 0; o4 < HID / 4; ++o4) {
        float a0 = cbp1[4*o4+0], a1 = cbp1[4*o4+1], a2 = cbp1[4*o4+2], a3 = cbp1[4*o4+3];
#pragma unroll
        for (int c = 0; c < IN_DIM; ++c) {
            float4 w = cWp1[c * (HID/4) + o4];
            float v = in[c];
            a0 = fmaf(v, w.x, a0); a1 = fmaf(v, w.y, a1);
            a2 = fmaf(v, w.z, a2); a3 = fmaf(v, w.w, a3);
        }
        h[4*o4+0] = gelu_exact(a0); h[4*o4+1] = gelu_exact(a1);
        h[4*o4+2] = gelu_exact(a2); h[4*o4+3] = gelu_exact(a3);
    }

    float4* xr = (float4*)(g_x + t * OUT_DIM);
#pragma unroll
    for (int o4 = 0; o4 < OUT_DIM / 4; ++o4) {
        float a0 = cbp2[4*o4+0], a1 = cbp2[4*o4+1], a2 = cbp2[4*o4+2], a3 = cbp2[4*o4+3];
#pragma unroll
        for (int c = 0; c < HID; ++c) {
            float4 w = cWp2[c * (OUT_DIM/4) + o4];
            float v = h[c];
            a0 = fmaf(v, w.x, a0); a1 = fmaf(v, w.y, a1);
            a2 = fmaf(v, w.z, a2); a3 = fmaf(v, w.w, a3);
        }
        float4 r; r.x = a0; r.y = a1; r.z = a2; r.w = a3;
        xr[o4] = r;
    }
}

// ---------------------------------------------------------------------------
// Kernel 2: neighbor MLP + mean over K + residual + LayerNorm
// One thread per (b,n,k) edge. 16 lanes = one node. Block = 8 nodes.
// Wk1, Wk2 from constant bank (76% of MACs); Wk3 from smem (24% -> crossbar
// load ~1 cyc per 128 MACs, balanced with fma pipe).
// ---------------------------------------------------------------------------
__global__ __launch_bounds__(128, 3) void edge_kernel(
    const float* __restrict__ igrid,   // (N,2)
    const float* __restrict__ ogrid,   // (N,2)
    const int*   __restrict__ nidx,    // (N,16)
    const float* __restrict__ Wk3,
    float* __restrict__ out)
{
    __shared__ float4 sW3[KH * OUT_DIM / 4];  // 64x32 -> 512 float4 (8192 B)

    int tid = threadIdx.x;
    {
        const float4* g3 = (const float4*)Wk3;
        for (int i = tid; i < KH * OUT_DIM / 4; i += 128) sW3[i] = g3[i];
    }
    __syncthreads();

    int r = tid >> 4;           // node within block (0..7)
    int k = tid & 15;           // neighbor index (0..15)
    int bn = blockIdx.x * 8 + r;     // 0 .. B*N-1
    int b  = bn >> 15;               // / 32768
    int n  = bn & (NN - 1);

    int nb = nidx[n * KK + k];

    // agg = [input_grid[nb], output_grid[n], f_y(32)]
    float agg[KIN];
    agg[0] = igrid[nb * 2 + 0];
    agg[1] = igrid[nb * 2 + 1];
    agg[2] = ogrid[n * 2 + 0];
    agg[3] = ogrid[n * 2 + 1];
    {
        const float4* xr = (const float4*)(g_x + (b * NN + nb) * OUT_DIM);
#pragma unroll
        for (int i = 0; i < OUT_DIM / 4; ++i) {
            float4 v = xr[i];
            agg[4 + 4*i + 0] = v.x; agg[4 + 4*i + 1] = v.y;
            agg[4 + 4*i + 2] = v.z; agg[4 + 4*i + 3] = v.w;
        }
    }

    // Layer 1: 36 -> 64, gelu  (weights: const bank)
    float h1[KH];
#pragma unroll
    for (int o4 = 0; o4 < KH / 4; ++o4) {
        float a0 = cbk1[4*o4+0], a1 = cbk1[4*o4+1], a2 = cbk1[4*o4+2], a3 = cbk1[4*o4+3];
#pragma unroll
        for (int c = 0; c < KIN; ++c) {
            float4 w = cWk1[c * (KH/4) + o4];
            float v = agg[c];
            a0 = fmaf(v, w.x, a0); a1 = fmaf(v, w.y, a1);
            a2 = fmaf(v, w.z, a2); a3 = fmaf(v, w.w, a3);
        }
        h1[4*o4+0] = gelu_exact(a0); h1[4*o4+1] = gelu_exact(a1);
        h1[4*o4+2] = gelu_exact(a2); h1[4*o4+3] = gelu_exact(a3);
    }

    // Layer 2: 64 -> 64, gelu  (weights: const bank)
    float h2[KH];
#pragma unroll
    for (int o4 = 0; o4 < KH / 4; ++o4) {
        float a0 = cbk2[4*o4+0], a1 = cbk2[4*o4+1], a2 = cbk2[4*o4+2], a3 = cbk2[4*o4+3];
#pragma unroll
        for (int c = 0; c < KH; ++c) {
            float4 w = cWk2[c * (KH/4) + o4];
            float v = h1[c];
            a0 = fmaf(v, w.x, a0); a1 = fmaf(v, w.y, a1);
            a2 = fmaf(v, w.z, a2); a3 = fmaf(v, w.w, a3);
        }
        h2[4*o4+0] = gelu_exact(a0); h2[4*o4+1] = gelu_exact(a1);
        h2[4*o4+2] = gelu_exact(a2); h2[4*o4+3] = gelu_exact(a3);
    }

    // Layer 3: 64 -> 32 (weights: smem), then reduce over K via shfl butterfly
    float kout[OUT_DIM];
#pragma unroll
    for (int o4 = 0; o4 < OUT_DIM / 4; ++o4) {
        float a0 = cbk3[4*o4+0], a1 = cbk3[4*o4+1], a2 = cbk3[4*o4+2], a3 = cbk3[4*o4+3];
#pragma unroll
        for (int c = 0; c < KH; ++c) {
            float4 w = sW3[c * (OUT_DIM/4) + o4];
            float v = h2[c];
            a0 = fmaf(v, w.x, a0); a1 = fmaf(v, w.y, a1);
            a2 = fmaf(v, w.z, a2); a3 = fmaf(v, w.w, a3);
        }
#pragma unroll
        for (int off = 8; off >= 1; off >>= 1) {
            a0 += __shfl_xor_sync(0xffffffffu, a0, off);
            a1 += __shfl_xor_sync(0xffffffffu, a1, off);
            a2 += __shfl_xor_sync(0xffffffffu, a2, off);
            a3 += __shfl_xor_sync(0xffffffffu, a3, off);
        }
        kout[4*o4+0] = a0; kout[4*o4+1] = a1;
        kout[4*o4+2] = a2; kout[4*o4+3] = a3;
    }

    // Lane 0 of each 16-lane group: mean over K, residual, LayerNorm, store
    if (k == 0) {
        float o[OUT_DIM];
        const float4* xr = (const float4*)(g_x + bn * OUT_DIM);
        float sum = 0.0f;
#pragma unroll
        for (int i = 0; i < OUT_DIM / 4; ++i) {
            float4 v = xr[i];
            o[4*i+0] = fmaf(kout[4*i+0], 0.0625f, v.x);
            o[4*i+1] = fmaf(kout[4*i+1], 0.0625f, v.y);
            o[4*i+2] = fmaf(kout[4*i+2], 0.0625f, v.z);
            o[4*i+3] = fmaf(kout[4*i+3], 0.0625f, v.w);
            sum += o[4*i+0] + o[4*i+1] + o[4*i+2] + o[4*i+3];
        }
        float mu = sum * (1.0f / OUT_DIM);
        float vs = 0.0f;
#pragma unroll
        for (int i = 0; i < OUT_DIM; ++i) {
            float d = o[i] - mu;
            vs = fmaf(d, d, vs);
        }
        float rs = rsqrtf(vs * (1.0f / OUT_DIM) + 1e-5f);

        float4* op = (float4*)(out + bn * OUT_DIM);
#pragma unroll
        for (int i = 0; i < OUT_DIM / 4; ++i) {
            float4 w;
            w.x = fmaf((o[4*i+0] - mu) * rs, cG[4*i+0], cBt[4*i+0]);
            w.y = fmaf((o[4*i+1] - mu) * rs, cG[4*i+1], cBt[4*i+1]);
            w.z = fmaf((o[4*i+2] - mu) * rs, cG[4*i+2], cBt[4*i+2]);
            w.w = fmaf((o[4*i+3] - mu) * rs, cG[4*i+3], cBt[4*i+3]);
            op[i] = w;
        }
    }
}

// ---------------------------------------------------------------------------
extern "C" void kernel_launch(void* const* d_in, const int* in_sizes, int n_in,
                              void* d_out, int out_size) {
    const float* inp   = (const float*)d_in[0];
    const float* igrid = (const float*)d_in[1];
    const float* ogrid = (const float*)d_in[2];
    const int*   nidx  = (const int*)  d_in[3];
    const float* Wp1   = (const float*)d_in[4];
    const float* bp1   = (const float*)d_in[5];
    const float* Wp2   = (const float*)d_in[6];
    const float* bp2   = (const float*)d_in[7];
    const float* Wk1   = (const float*)d_in[8];
    const float* bk1   = (const float*)d_in[9];
    const float* Wk2   = (const float*)d_in[10];
    const float* bk2   = (const float*)d_in[11];
    const float* Wk3   = (const float*)d_in[12];
    const float* bk3   = (const float*)d_in[13];
    const float* ln_g  = (const float*)d_in[14];
    const float* ln_b  = (const float*)d_in[15];
    float* out = (float*)d_out;

    // Stage warp-uniform weights into the constant bank (D2D async, capturable)
    cudaMemcpyToSymbolAsync(cWk1, Wk1, KIN * KH * sizeof(float), 0, cudaMemcpyDeviceToDevice);
    cudaMemcpyToSymbolAsync(cWk2, Wk2, KH * KH * sizeof(float), 0, cudaMemcpyDeviceToDevice);
    cudaMemcpyToSymbolAsync(cbk1, bk1, KH * sizeof(float), 0, cudaMemcpyDeviceToDevice);
    cudaMemcpyToSymbolAsync(cbk2, bk2, KH * sizeof(float), 0, cudaMemcpyDeviceToDevice);
    cudaMemcpyToSymbolAsync(cbk3, bk3, OUT_DIM * sizeof(float), 0, cudaMemcpyDeviceToDevice);
    cudaMemcpyToSymbolAsync(cG,   ln_g, OUT_DIM * sizeof(float), 0, cudaMemcpyDeviceToDevice);
    cudaMemcpyToSymbolAsync(cBt,  ln_b, OUT_DIM * sizeof(float), 0, cudaMemcpyDeviceToDevice);
    cudaMemcpyToSymbolAsync(cWp1, Wp1, IN_DIM * HID * sizeof(float), 0, cudaMemcpyDeviceToDevice);
    cudaMemcpyToSymbolAsync(cWp2, Wp2, HID * OUT_DIM * sizeof(float), 0, cudaMemcpyDeviceToDevice);
    cudaMemcpyToSymbolAsync(cbp1, bp1, HID * sizeof(float), 0, cudaMemcpyDeviceToDevice);
    cudaMemcpyToSymbolAsync(cbp2, bp2, OUT_DIM * sizeof(float), 0, cudaMemcpyDeviceToDevice);

    pointwise_kernel<<<(BB * NN) / 256, 256>>>(inp);
    edge_kernel<<<(BB * NN) / 8, 128>>>(igrid, ogrid, nidx, Wk3, out);
}

// round 3
// speedup vs baseline: 1.3133x; 1.3133x over previous
#include <cuda_runtime.h>
#include <math.h>

// Problem constants
#define BB 4
#define NN 32768
#define KK 16
#define IN_DIM 32
#define HID 64
#define OUT_DIM 32
#define KIN 36
#define KH 64

typedef unsigned long long ull;

// Scratch for pointwise-MLP output x: (B, N, 32) floats = 16 MB
__device__ float g_x[BB * NN * OUT_DIM];

// ---------------------------------------------------------------------------
// Constant-bank copies (LDC port) — also mirrored to smem (LSU port) in the
// edge kernel; loads alternate ports on c-parity so neither port exceeds the
// halved fma-pipe time of packed FFMA2 math.
// ---------------------------------------------------------------------------
__constant__ ulonglong2 cWk1[KIN * KH / 4];       //  9216 B
__constant__ ulonglong2 cWk2[KH * KH / 4];        // 16384 B
__constant__ ulonglong2 cWk3[KH * OUT_DIM / 4];   //  8192 B
__constant__ float  cbk1[KH];
__constant__ float  cbk2[KH];
__constant__ float  cbk3[OUT_DIM];
__constant__ float  cG[OUT_DIM];
__constant__ float  cBt[OUT_DIM];
__constant__ ulonglong2 cWp1[IN_DIM * HID / 4];   //  8192 B
__constant__ ulonglong2 cWp2[HID * OUT_DIM / 4];  //  8192 B
__constant__ float  cbp1[HID];
__constant__ float  cbp2[OUT_DIM];

// ---------------------------------------------------------------------------
// Packed f32x2 helpers (FFMA2 — only reachable via PTX fma.rn.f32x2)
// ---------------------------------------------------------------------------
__device__ __forceinline__ ull ffma2(ull a, ull b, ull c) {
    ull d;
    asm("fma.rn.f32x2 %0, %1, %2, %3;" : "=l"(d) : "l"(a), "l"(b), "l"(c));
    return d;
}
__device__ __forceinline__ ull fadd2(ull a, ull b) {
    ull d;
    asm("add.rn.f32x2 %0, %1, %2;" : "=l"(d) : "l"(a), "l"(b));
    return d;
}
__device__ __forceinline__ ull pack_dup(float v) {
    ull d;
    asm("mov.b64 %0, {%1, %1};" : "=l"(d) : "r"(__float_as_uint(v)));
    return d;
}
__device__ __forceinline__ ull pack2(float lo, float hi) {
    ull d;
    asm("mov.b64 %0, {%1, %2};" : "=l"(d) : "r"(__float_as_uint(lo)), "r"(__float_as_uint(hi)));
    return d;
}
__device__ __forceinline__ void unpack2(ull p, float& lo, float& hi) {
    unsigned int a, b;
    asm("mov.b64 {%0, %1}, %2;" : "=r"(a), "=r"(b) : "l"(p));
    lo = __uint_as_float(a); hi = __uint_as_float(b);
}

__device__ __forceinline__ float gelu_exact(float v) {
    return 0.5f * v * (1.0f + erff(v * 0.7071067811865476f));
}

// ---------------------------------------------------------------------------
// Kernel 1: pointwise MLP (packed math, const weights) — small fraction of time
// ---------------------------------------------------------------------------
__global__ __launch_bounds__(256) void pointwise_kernel(
    const float* __restrict__ inp)
{
    int t = blockIdx.x * 256 + threadIdx.x;   // 0 .. B*N-1
    const float4* ir = (const float4*)(inp + t * IN_DIM);

    float in[IN_DIM];
#pragma unroll
    for (int i = 0; i < IN_DIM / 4; ++i) {
        float4 v = ir[i];
        in[4*i+0] = v.x; in[4*i+1] = v.y; in[4*i+2] = v.z; in[4*i+3] = v.w;
    }

    // Layer p1: 32 -> 64
    ull acc[HID/2];
#pragma unroll
    for (int i = 0; i < HID/2; ++i) acc[i] = pack2(cbp1[2*i], cbp1[2*i+1]);
#pragma unroll
    for (int c = 0; c < IN_DIM; ++c) {
        ull v = pack_dup(in[c]);
#pragma unroll
        for (int o2 = 0; o2 < HID/4; ++o2) {
            ulonglong2 w = cWp1[c * (HID/4) + o2];
            acc[2*o2+0] = ffma2(v, w.x, acc[2*o2+0]);
            acc[2*o2+1] = ffma2(v, w.y, acc[2*o2+1]);
        }
    }
    float h[HID];
#pragma unroll
    for (int i = 0; i < HID/2; ++i) {
        float a, b; unpack2(acc[i], a, b);
        h[2*i] = gelu_exact(a); h[2*i+1] = gelu_exact(b);
    }

    // Layer p2: 64 -> 32
    ull acc2[OUT_DIM/2];
#pragma unroll
    for (int i = 0; i < OUT_DIM/2; ++i) acc2[i] = pack2(cbp2[2*i], cbp2[2*i+1]);
#pragma unroll
    for (int c = 0; c < HID; ++c) {
        ull v = pack_dup(h[c]);
#pragma unroll
        for (int o2 = 0; o2 < OUT_DIM/4; ++o2) {
            ulonglong2 w = cWp2[c * (OUT_DIM/4) + o2];
            acc2[2*o2+0] = ffma2(v, w.x, acc2[2*o2+0]);
            acc2[2*o2+1] = ffma2(v, w.y, acc2[2*o2+1]);
        }
    }
    ulonglong2* xr = (ulonglong2*)(g_x + t * OUT_DIM);
#pragma unroll
    for (int o2 = 0; o2 < OUT_DIM/4; ++o2) {
        ulonglong2 r; r.x = acc2[2*o2+0]; r.y = acc2[2*o2+1];
        xr[o2] = r;
    }
}

// ---------------------------------------------------------------------------
// Kernel 2: neighbor MLP + mean over K + residual + LayerNorm
// One thread per (b,n,k) edge; 16 lanes = one node; block = 8 nodes.
// Packed f32x2 accumulators; weight loads alternate const/smem on c-parity.
// ---------------------------------------------------------------------------
__global__ __launch_bounds__(128, 3) void edge_kernel(
    const float* __restrict__ igrid,   // (N,2)
    const float* __restrict__ ogrid,   // (N,2)
    const int*   __restrict__ nidx,    // (N,16)
    const float* __restrict__ Wk1,
    const float* __restrict__ Wk2,
    const float* __restrict__ Wk3,
    float* __restrict__ out)
{
    __shared__ ulonglong2 sW1[KIN * KH / 4];      //  9216 B
    __shared__ ulonglong2 sW2[KH * KH / 4];       // 16384 B
    __shared__ ulonglong2 sW3[KH * OUT_DIM / 4];  //  8192 B

    int tid = threadIdx.x;
    {
        const ulonglong2* g1 = (const ulonglong2*)Wk1;
        const ulonglong2* g2 = (const ulonglong2*)Wk2;
        const ulonglong2* g3 = (const ulonglong2*)Wk3;
        for (int i = tid; i < KIN * KH / 4; i += 128) sW1[i] = g1[i];
        for (int i = tid; i < KH * KH / 4; i += 128) sW2[i] = g2[i];
        for (int i = tid; i < KH * OUT_DIM / 4; i += 128) sW3[i] = g3[i];
    }
    __syncthreads();

    int r = tid >> 4;                // node within block (0..7)
    int k = tid & 15;                // neighbor index (0..15)
    int bn = blockIdx.x * 8 + r;     // 0 .. B*N-1
    int b  = bn >> 15;               // / 32768
    int n  = bn & (NN - 1);

    int nb = nidx[n * KK + k];

    // agg = [input_grid[nb], output_grid[n], f_y(32)]
    float agg[KIN];
    agg[0] = igrid[nb * 2 + 0];
    agg[1] = igrid[nb * 2 + 1];
    agg[2] = ogrid[n * 2 + 0];
    agg[3] = ogrid[n * 2 + 1];
    {
        const float4* xr = (const float4*)(g_x + (b * NN + nb) * OUT_DIM);
#pragma unroll
        for (int i = 0; i < OUT_DIM / 4; ++i) {
            float4 v = xr[i];
            agg[4 + 4*i + 0] = v.x; agg[4 + 4*i + 1] = v.y;
            agg[4 + 4*i + 2] = v.z; agg[4 + 4*i + 3] = v.w;
        }
    }

    // ---- Layer 1: 36 -> 64, gelu (loads alternate const/smem on c-parity)
    float h1[KH];
    {
        ull acc[KH/2];
#pragma unroll
        for (int i = 0; i < KH/2; ++i) acc[i] = pack2(cbk1[2*i], cbk1[2*i+1]);
#pragma unroll
        for (int c = 0; c < KIN; ++c) {
            ull v = pack_dup(agg[c]);
#pragma unroll
            for (int o2 = 0; o2 < KH/4; ++o2) {
                ulonglong2 w;
                if (c & 1) w = sW1[c * (KH/4) + o2];
                else       w = cWk1[c * (KH/4) + o2];
                acc[2*o2+0] = ffma2(v, w.x, acc[2*o2+0]);
                acc[2*o2+1] = ffma2(v, w.y, acc[2*o2+1]);
            }
        }
#pragma unroll
        for (int i = 0; i < KH/2; ++i) {
            float a, bq; unpack2(acc[i], a, bq);
            h1[2*i] = gelu_exact(a); h1[2*i+1] = gelu_exact(bq);
        }
    }

    // ---- Layer 2: 64 -> 64, gelu
    float h2[KH];
    {
        ull acc[KH/2];
#pragma unroll
        for (int i = 0; i < KH/2; ++i) acc[i] = pack2(cbk2[2*i], cbk2[2*i+1]);
#pragma unroll
        for (int c = 0; c < KH; ++c) {
            ull v = pack_dup(h1[c]);
#pragma unroll
            for (int o2 = 0; o2 < KH/4; ++o2) {
                ulonglong2 w;
                if (c & 1) w = sW2[c * (KH/4) + o2];
                else       w = cWk2[c * (KH/4) + o2];
                acc[2*o2+0] = ffma2(v, w.x, acc[2*o2+0]);
                acc[2*o2+1] = ffma2(v, w.y, acc[2*o2+1]);
            }
        }
#pragma unroll
        for (int i = 0; i < KH/2; ++i) {
            float a, bq; unpack2(acc[i], a, bq);
            h2[2*i] = gelu_exact(a); h2[2*i+1] = gelu_exact(bq);
        }
    }

    // ---- Layer 3: 64 -> 32, then mean over K via packed shfl butterfly
    ull kacc[OUT_DIM/2];
#pragma unroll
    for (int i = 0; i < OUT_DIM/2; ++i) kacc[i] = pack2(cbk3[2*i], cbk3[2*i+1]);
#pragma unroll
    for (int c = 0; c < KH; ++c) {
        ull v = pack_dup(h2[c]);
#pragma unroll
        for (int o2 = 0; o2 < OUT_DIM/4; ++o2) {
            ulonglong2 w;
            if (c & 1) w = sW3[c * (OUT_DIM/4) + o2];
            else       w = cWk3[c * (OUT_DIM/4) + o2];
            kacc[2*o2+0] = ffma2(v, w.x, kacc[2*o2+0]);
            kacc[2*o2+1] = ffma2(v, w.y, kacc[2*o2+1]);
        }
    }
#pragma unroll
    for (int off = 8; off >= 1; off >>= 1) {
#pragma unroll
        for (int i = 0; i < OUT_DIM/2; ++i) {
            ull other = __shfl_xor_sync(0xffffffffu, kacc[i], off);
            kacc[i] = fadd2(kacc[i], other);
        }
    }

    // Lane 0 of each 16-lane group: mean over K, residual, LayerNorm, store
    if (k == 0) {
        float kout[OUT_DIM];
#pragma unroll
        for (int i = 0; i < OUT_DIM/2; ++i) unpack2(kacc[i], kout[2*i], kout[2*i+1]);

        float o[OUT_DIM];
        const float4* xr = (const float4*)(g_x + bn * OUT_DIM);
        float sum = 0.0f;
#pragma unroll
        for (int i = 0; i < OUT_DIM / 4; ++i) {
            float4 v = xr[i];
            o[4*i+0] = fmaf(kout[4*i+0], 0.0625f, v.x);
            o[4*i+1] = fmaf(kout[4*i+1], 0.0625f, v.y);
            o[4*i+2] = fmaf(kout[4*i+2], 0.0625f, v.z);
            o[4*i+3] = fmaf(kout[4*i+3], 0.0625f, v.w);
            sum += o[4*i+0] + o[4*i+1] + o[4*i+2] + o[4*i+3];
        }
        float mu = sum * (1.0f / OUT_DIM);
        float vs = 0.0f;
#pragma unroll
        for (int i = 0; i < OUT_DIM; ++i) {
            float d = o[i] - mu;
            vs = fmaf(d, d, vs);
        }
        float rs = rsqrtf(vs * (1.0f / OUT_DIM) + 1e-5f);

        float4* op = (float4*)(out + bn * OUT_DIM);
#pragma unroll
        for (int i = 0; i < OUT_DIM / 4; ++i) {
            float4 w;
            w.x = fmaf((o[4*i+0] - mu) * rs, cG[4*i+0], cBt[4*i+0]);
            w.y = fmaf((o[4*i+1] - mu) * rs, cG[4*i+1], cBt[4*i+1]);
            w.z = fmaf((o[4*i+2] - mu) * rs, cG[4*i+2], cBt[4*i+2]);
            w.w = fmaf((o[4*i+3] - mu) * rs, cG[4*i+3], cBt[4*i+3]);
            op[i] = w;
        }
    }
}

// ---------------------------------------------------------------------------
extern "C" void kernel_launch(void* const* d_in, const int* in_sizes, int n_in,
                              void* d_out, int out_size) {
    const float* inp   = (const float*)d_in[0];
    const float* igrid = (const float*)d_in[1];
    const float* ogrid = (const float*)d_in[2];
    const int*   nidx  = (const int*)  d_in[3];
    const float* Wp1   = (const float*)d_in[4];
    const float* bp1   = (const float*)d_in[5];
    const float* Wp2   = (const float*)d_in[6];
    const float* bp2   = (const float*)d_in[7];
    const float* Wk1   = (const float*)d_in[8];
    const float* bk1   = (const float*)d_in[9];
    const float* Wk2   = (const float*)d_in[10];
    const float* bk2   = (const float*)d_in[11];
    const float* Wk3   = (const float*)d_in[12];
    const float* bk3   = (const float*)d_in[13];
    const float* ln_g  = (const float*)d_in[14];
    const float* ln_b  = (const float*)d_in[15];
    float* out = (float*)d_out;

    // Stage weights into the constant bank (D2D async, graph-capturable)
    cudaMemcpyToSymbolAsync(cWk1, Wk1, KIN * KH * sizeof(float), 0, cudaMemcpyDeviceToDevice);
    cudaMemcpyToSymbolAsync(cWk2, Wk2, KH * KH * sizeof(float), 0, cudaMemcpyDeviceToDevice);
    cudaMemcpyToSymbolAsync(cWk3, Wk3, KH * OUT_DIM * sizeof(float), 0, cudaMemcpyDeviceToDevice);
    cudaMemcpyToSymbolAsync(cbk1, bk1, KH * sizeof(float), 0, cudaMemcpyDeviceToDevice);
    cudaMemcpyToSymbolAsync(cbk2, bk2, KH * sizeof(float), 0, cudaMemcpyDeviceToDevice);
    cudaMemcpyToSymbolAsync(cbk3, bk3, OUT_DIM * sizeof(float), 0, cudaMemcpyDeviceToDevice);
    cudaMemcpyToSymbolAsync(cG,   ln_g, OUT_DIM * sizeof(float), 0, cudaMemcpyDeviceToDevice);
    cudaMemcpyToSymbolAsync(cBt,  ln_b, OUT_DIM * sizeof(float), 0, cudaMemcpyDeviceToDevice);
    cudaMemcpyToSymbolAsync(cWp1, Wp1, IN_DIM * HID * sizeof(float), 0, cudaMemcpyDeviceToDevice);
    cudaMemcpyToSymbolAsync(cWp2, Wp2, HID * OUT_DIM * sizeof(float), 0, cudaMemcpyDeviceToDevice);
    cudaMemcpyToSymbolAsync(cbp1, bp1, HID * sizeof(float), 0, cudaMemcpyDeviceToDevice);
    cudaMemcpyToSymbolAsync(cbp2, bp2, OUT_DIM * sizeof(float), 0, cudaMemcpyDeviceToDevice);

    pointwise_kernel<<<(BB * NN) / 256, 256>>>(inp);
    edge_kernel<<<(BB * NN) / 8, 128>>>(igrid, ogrid, nidx, Wk1, Wk2, Wk3, out);
}

// round 4
// speedup vs baseline: 1.6737x; 1.2745x over previous
#include <cuda_runtime.h>
#include <math.h>

// Problem constants
#define BB 4
#define NN 32768
#define KK 16
#define IN_DIM 32
#define HID 64
#define OUT_DIM 32
#define KIN 36
#define KH 64

typedef unsigned long long ull;

// Scratch for pointwise-MLP output x: (B, N, 32) floats = 16 MB
__device__ float g_x[BB * NN * OUT_DIM];

// Constant-bank copies (LDC port); smem mirrors carry the other half of loads.
__constant__ ulonglong2 cWk1[KIN * KH / 4];       //  9216 B
__constant__ ulonglong2 cWk2[KH * KH / 4];        // 16384 B
__constant__ ulonglong2 cWk3[KH * OUT_DIM / 4];   //  8192 B
__constant__ float  cbk1[KH];
__constant__ float  cbk2[KH];
__constant__ float  cbk3[OUT_DIM];
__constant__ float  cG[OUT_DIM];
__constant__ float  cBt[OUT_DIM];
__constant__ ulonglong2 cWp1[IN_DIM * HID / 4];   //  8192 B
__constant__ ulonglong2 cWp2[HID * OUT_DIM / 4];  //  8192 B
__constant__ float  cbp1[HID];
__constant__ float  cbp2[OUT_DIM];

// Packed f32x2 helpers (FFMA2 — PTX-only)
__device__ __forceinline__ ull ffma2(ull a, ull b, ull c) {
    ull d;
    asm("fma.rn.f32x2 %0, %1, %2, %3;" : "=l"(d) : "l"(a), "l"(b), "l"(c));
    return d;
}
__device__ __forceinline__ ull fadd2(ull a, ull b) {
    ull d;
    asm("add.rn.f32x2 %0, %1, %2;" : "=l"(d) : "l"(a), "l"(b));
    return d;
}
__device__ __forceinline__ ull pack_dup(float v) {
    ull d;
    asm("mov.b64 %0, {%1, %1};" : "=l"(d) : "r"(__float_as_uint(v)));
    return d;
}
__device__ __forceinline__ ull pack2(float lo, float hi) {
    ull d;
    asm("mov.b64 %0, {%1, %2};" : "=l"(d) : "r"(__float_as_uint(lo)), "r"(__float_as_uint(hi)));
    return d;
}
__device__ __forceinline__ void unpack2(ull p, float& lo, float& hi) {
    unsigned int a, b;
    asm("mov.b64 {%0, %1}, %2;" : "=r"(a), "=r"(b) : "l"(p));
    lo = __uint_as_float(a); hi = __uint_as_float(b);
}

__device__ __forceinline__ float gelu_exact(float v) {
    return 0.5f * v * (1.0f + erff(v * 0.7071067811865476f));
}

// ---------------------------------------------------------------------------
// Kernel 1: pointwise MLP (packed math, const weights)
// ---------------------------------------------------------------------------
__global__ __launch_bounds__(256) void pointwise_kernel(
    const float* __restrict__ inp)
{
    int t = blockIdx.x * 256 + threadIdx.x;   // 0 .. B*N-1
    const float4* ir = (const float4*)(inp + t * IN_DIM);

    float in[IN_DIM];
#pragma unroll
    for (int i = 0; i < IN_DIM / 4; ++i) {
        float4 v = ir[i];
        in[4*i+0] = v.x; in[4*i+1] = v.y; in[4*i+2] = v.z; in[4*i+3] = v.w;
    }

    ull acc[HID/2];
#pragma unroll
    for (int i = 0; i < HID/2; ++i) acc[i] = pack2(cbp1[2*i], cbp1[2*i+1]);
#pragma unroll
    for (int c = 0; c < IN_DIM; ++c) {
        ull v = pack_dup(in[c]);
#pragma unroll
        for (int o2 = 0; o2 < HID/4; ++o2) {
            ulonglong2 w = cWp1[c * (HID/4) + o2];
            acc[2*o2+0] = ffma2(v, w.x, acc[2*o2+0]);
            acc[2*o2+1] = ffma2(v, w.y, acc[2*o2+1]);
        }
    }
    float h[HID];
#pragma unroll
    for (int i = 0; i < HID/2; ++i) {
        float a, b; unpack2(acc[i], a, b);
        h[2*i] = gelu_exact(a); h[2*i+1] = gelu_exact(b);
    }

    ull acc2[OUT_DIM/2];
#pragma unroll
    for (int i = 0; i < OUT_DIM/2; ++i) acc2[i] = pack2(cbp2[2*i], cbp2[2*i+1]);
#pragma unroll
    for (int c = 0; c < HID; ++c) {
        ull v = pack_dup(h[c]);
#pragma unroll
        for (int o2 = 0; o2 < OUT_DIM/4; ++o2) {
            ulonglong2 w = cWp2[c * (OUT_DIM/4) + o2];
            acc2[2*o2+0] = ffma2(v, w.x, acc2[2*o2+0]);
            acc2[2*o2+1] = ffma2(v, w.y, acc2[2*o2+1]);
        }
    }
    ulonglong2* xr = (ulonglong2*)(g_x + t * OUT_DIM);
#pragma unroll
    for (int o2 = 0; o2 < OUT_DIM/4; ++o2) {
        ulonglong2 r; r.x = acc2[2*o2+0]; r.y = acc2[2*o2+1];
        xr[o2] = r;
    }
}

// ---------------------------------------------------------------------------
// Kernel 2: edge MLP, register-lean version (<=128 regs -> 4 CTAs/SM).
//  - Layer 1 computed in two 32-channel output chunks.
//  - Layers 2+3 fused: 8 h2-channels at a time, streamed straight into the
//    layer-3 accumulators (h2 never materializes as a 64-float array).
//  - Weight loads alternate const-bank (even c) / smem (odd c).
// ---------------------------------------------------------------------------
__global__ __launch_bounds__(128, 4) void edge_kernel(
    const float* __restrict__ igrid,   // (N,2)
    const float* __restrict__ ogrid,   // (N,2)
    const int*   __restrict__ nidx,    // (N,16)
    const float* __restrict__ Wk1,
    const float* __restrict__ Wk2,
    const float* __restrict__ Wk3,
    float* __restrict__ out)
{
    __shared__ ulonglong2 sW1[KIN * KH / 4];      //  9216 B
    __shared__ ulonglong2 sW2[KH * KH / 4];       // 16384 B
    __shared__ ulonglong2 sW3[KH * OUT_DIM / 4];  //  8192 B

    int tid = threadIdx.x;
    {
        const ulonglong2* g1 = (const ulonglong2*)Wk1;
        const ulonglong2* g2 = (const ulonglong2*)Wk2;
        const ulonglong2* g3 = (const ulonglong2*)Wk3;
        for (int i = tid; i < KIN * KH / 4; i += 128) sW1[i] = g1[i];
        for (int i = tid; i < KH * KH / 4; i += 128) sW2[i] = g2[i];
        for (int i = tid; i < KH * OUT_DIM / 4; i += 128) sW3[i] = g3[i];
    }
    __syncthreads();

    int r = tid >> 4;                // node within block (0..7)
    int k = tid & 15;                // neighbor index (0..15)
    int bn = blockIdx.x * 8 + r;     // 0 .. B*N-1
    int b  = bn >> 15;               // / 32768
    int n  = bn & (NN - 1);

    int nb = nidx[n * KK + k];

    float h1[KH];   // after layer 1; before that, first 36 slots hold agg

    // agg = [input_grid[nb], output_grid[n], f_y(32)]  (stored in h1[0..35])
    {
        h1[0] = igrid[nb * 2 + 0];
        h1[1] = igrid[nb * 2 + 1];
        h1[2] = ogrid[n * 2 + 0];
        h1[3] = ogrid[n * 2 + 1];
        const float4* xr = (const float4*)(g_x + (b * NN + nb) * OUT_DIM);
#pragma unroll
        for (int i = 0; i < OUT_DIM / 4; ++i) {
            float4 v = xr[i];
            h1[4 + 4*i + 0] = v.x; h1[4 + 4*i + 1] = v.y;
            h1[4 + 4*i + 2] = v.z; h1[4 + 4*i + 3] = v.w;
        }
    }

    // ---- Layer 1: 36 -> 64, gelu; two output chunks of 32 channels.
    // Write results into h1[] from the top down so agg (h1[0..35]) stays
    // intact until fully consumed: chunk 1 (ch=1) writes h1[32..63] first.
    {
        float agg[KIN];
#pragma unroll
        for (int i = 0; i < KIN; ++i) agg[i] = h1[i];

#pragma unroll
        for (int ch = 1; ch >= 0; --ch) {
            ull acc[16];
#pragma unroll
            for (int i = 0; i < 16; ++i)
                acc[i] = pack2(cbk1[32*ch + 2*i], cbk1[32*ch + 2*i + 1]);
#pragma unroll
            for (int c = 0; c < KIN; ++c) {
                ull v = pack_dup(agg[c]);
#pragma unroll
                for (int o2 = 0; o2 < 8; ++o2) {
                    ulonglong2 w;
                    int idx = c * (KH/4) + ch * 8 + o2;
                    if (c & 1) w = sW1[idx];
                    else       w = cWk1[idx];
                    acc[2*o2+0] = ffma2(v, w.x, acc[2*o2+0]);
                    acc[2*o2+1] = ffma2(v, w.y, acc[2*o2+1]);
                }
            }
#pragma unroll
            for (int i = 0; i < 16; ++i) {
                float a, bq; unpack2(acc[i], a, bq);
                h1[32*ch + 2*i]     = gelu_exact(a);
                h1[32*ch + 2*i + 1] = gelu_exact(bq);
            }
        }
    }

    // ---- Layers 2+3 fused: 8 h2-channels per chunk -> straight into kacc.
    ull kacc[OUT_DIM/2];
#pragma unroll
    for (int i = 0; i < OUT_DIM/2; ++i) kacc[i] = pack2(cbk3[2*i], cbk3[2*i+1]);

#pragma unroll
    for (int ch = 0; ch < 8; ++ch) {
        ull acc[4];
#pragma unroll
        for (int i = 0; i < 4; ++i)
            acc[i] = pack2(cbk2[8*ch + 2*i], cbk2[8*ch + 2*i + 1]);
#pragma unroll
        for (int c = 0; c < KH; ++c) {
            ull v = pack_dup(h1[c]);
#pragma unroll
            for (int o2 = 0; o2 < 2; ++o2) {
                ulonglong2 w;
                int idx = c * (KH/4) + ch * 2 + o2;
                if (c & 1) w = sW2[idx];
                else       w = cWk2[idx];
                acc[2*o2+0] = ffma2(v, w.x, acc[2*o2+0]);
                acc[2*o2+1] = ffma2(v, w.y, acc[2*o2+1]);
            }
        }
        float t[8];
#pragma unroll
        for (int i = 0; i < 4; ++i) {
            float a, bq; unpack2(acc[i], a, bq);
            t[2*i] = gelu_exact(a); t[2*i+1] = gelu_exact(bq);
        }
        // Stream these 8 h2-channels into the layer-3 accumulators
#pragma unroll
        for (int cc = 0; cc < 8; ++cc) {
            int c3 = 8*ch + cc;
            ull v = pack_dup(t[cc]);
#pragma unroll
            for (int o2 = 0; o2 < OUT_DIM/4; ++o2) {
                ulonglong2 w;
                int idx = c3 * (OUT_DIM/4) + o2;
                if (c3 & 1) w = sW3[idx];
                else        w = cWk3[idx];
                kacc[2*o2+0] = ffma2(v, w.x, kacc[2*o2+0]);
                kacc[2*o2+1] = ffma2(v, w.y, kacc[2*o2+1]);
            }
        }
    }

    // Mean over K via packed shfl butterfly (16 lanes per node)
#pragma unroll
    for (int off = 8; off >= 1; off >>= 1) {
#pragma unroll
        for (int i = 0; i < OUT_DIM/2; ++i) {
            ull other = __shfl_xor_sync(0xffffffffu, kacc[i], off);
            kacc[i] = fadd2(kacc[i], other);
        }
    }

    // Lane 0 of each 16-lane group: mean, residual, LayerNorm, store
    if (k == 0) {
        float kout[OUT_DIM];
#pragma unroll
        for (int i = 0; i < OUT_DIM/2; ++i) unpack2(kacc[i], kout[2*i], kout[2*i+1]);

        float o[OUT_DIM];
        const float4* xr = (const float4*)(g_x + bn * OUT_DIM);
        float sum = 0.0f;
#pragma unroll
        for (int i = 0; i < OUT_DIM / 4; ++i) {
            float4 v = xr[i];
            o[4*i+0] = fmaf(kout[4*i+0], 0.0625f, v.x);
            o[4*i+1] = fmaf(kout[4*i+1], 0.0625f, v.y);
            o[4*i+2] = fmaf(kout[4*i+2], 0.0625f, v.z);
            o[4*i+3] = fmaf(kout[4*i+3], 0.0625f, v.w);
            sum += o[4*i+0] + o[4*i+1] + o[4*i+2] + o[4*i+3];
        }
        float mu = sum * (1.0f / OUT_DIM);
        float vs = 0.0f;
#pragma unroll
        for (int i = 0; i < OUT_DIM; ++i) {
            float d = o[i] - mu;
            vs = fmaf(d, d, vs);
        }
        float rs = rsqrtf(vs * (1.0f / OUT_DIM) + 1e-5f);

        float4* op = (float4*)(out + bn * OUT_DIM);
#pragma unroll
        for (int i = 0; i < OUT_DIM / 4; ++i) {
            float4 w;
            w.x = fmaf((o[4*i+0] - mu) * rs, cG[4*i+0], cBt[4*i+0]);
            w.y = fmaf((o[4*i+1] - mu) * rs, cG[4*i+1], cBt[4*i+1]);
            w.z = fmaf((o[4*i+2] - mu) * rs, cG[4*i+2], cBt[4*i+2]);
            w.w = fmaf((o[4*i+3] - mu) * rs, cG[4*i+3], cBt[4*i+3]);
            op[i] = w;
        }
    }
}

// ---------------------------------------------------------------------------
extern "C" void kernel_launch(void* const* d_in, const int* in_sizes, int n_in,
                              void* d_out, int out_size) {
    const float* inp   = (const float*)d_in[0];
    const float* igrid = (const float*)d_in[1];
    const float* ogrid = (const float*)d_in[2];
    const int*   nidx  = (const int*)  d_in[3];
    const float* Wp1   = (const float*)d_in[4];
    const float* bp1   = (const float*)d_in[5];
    const float* Wp2   = (const float*)d_in[6];
    const float* bp2   = (const float*)d_in[7];
    const float* Wk1   = (const float*)d_in[8];
    const float* bk1   = (const float*)d_in[9];
    const float* Wk2   = (const float*)d_in[10];
    const float* bk2   = (const float*)d_in[11];
    const float* Wk3   = (const float*)d_in[12];
    const float* bk3   = (const float*)d_in[13];
    const float* ln_g  = (const float*)d_in[14];
    const float* ln_b  = (const float*)d_in[15];
    float* out = (float*)d_out;

    cudaMemcpyToSymbolAsync(cWk1, Wk1, KIN * KH * sizeof(float), 0, cudaMemcpyDeviceToDevice);
    cudaMemcpyToSymbolAsync(cWk2, Wk2, KH * KH * sizeof(float), 0, cudaMemcpyDeviceToDevice);
    cudaMemcpyToSymbolAsync(cWk3, Wk3, KH * OUT_DIM * sizeof(float), 0, cudaMemcpyDeviceToDevice);
    cudaMemcpyToSymbolAsync(cbk1, bk1, KH * sizeof(float), 0, cudaMemcpyDeviceToDevice);
    cudaMemcpyToSymbolAsync(cbk2, bk2, KH * sizeof(float), 0, cudaMemcpyDeviceToDevice);
    cudaMemcpyToSymbolAsync(cbk3, bk3, OUT_DIM * sizeof(float), 0, cudaMemcpyDeviceToDevice);
    cudaMemcpyToSymbolAsync(cG,   ln_g, OUT_DIM * sizeof(float), 0, cudaMemcpyDeviceToDevice);
    cudaMemcpyToSymbolAsync(cBt,  ln_b, OUT_DIM * sizeof(float), 0, cudaMemcpyDeviceToDevice);
    cudaMemcpyToSymbolAsync(cWp1, Wp1, IN_DIM * HID * sizeof(float), 0, cudaMemcpyDeviceToDevice);
    cudaMemcpyToSymbolAsync(cWp2, Wp2, HID * OUT_DIM * sizeof(float), 0, cudaMemcpyDeviceToDevice);
    cudaMemcpyToSymbolAsync(cbp1, bp1, HID * sizeof(float), 0, cudaMemcpyDeviceToDevice);
    cudaMemcpyToSymbolAsync(cbp2, bp2, OUT_DIM * sizeof(float), 0, cudaMemcpyDeviceToDevice);

    pointwise_kernel<<<(BB * NN) / 256, 256>>>(inp);
    edge_kernel<<<(BB * NN) / 8, 128>>>(igrid, ogrid, nidx, Wk1, Wk2, Wk3, out);
}